// round 12
// baseline (speedup 1.0000x reference)
#include <cuda_runtime.h>
#include <float.h>

// Problem constants
#define B      2
#define C      3
#define T      8
#define H      448
#define W      448
#define NKEY   4
#define L      196      // 14*14
#define GH     14
#define R      121      // 11*11
#define NS     500
#define BK     (B*NKEY) // 8
#define OUTHW  128      // s*A

// Device scratch (no allocation allowed)
__device__ float g_scn[BK][R];   // normalized region scores (producer block writes)
__device__ int   g_cnt[BK][R];   // top-1 histogram (zeroed by producer each launch)
__device__ int   g_flag[BK];     // handshake flags: 0 at module load; gather resets
                                 // them each launch, so every replay starts at 0.

// ---------------------------------------------------------------------------
// Kernel 1 (R10-proven): fused score-norm + perturbed top-1 argmax.
// grid = (63, 8), block = 256. Single wave => intra-kernel handshake safe:
//   block x==0 per key computes normalized scores -> g_scn, zeroes g_cnt,
//   fences, raises g_flag[bk]; other blocks poll then read g_scn.
// One warp per sample; atomic histogram (order-independent => deterministic).
// ---------------------------------------------------------------------------
__global__ void argmax_kernel(const float* __restrict__ score,
                              const float* __restrict__ noise,
                              const float* __restrict__ sigma_p)
{
    const int bk   = blockIdx.y;
    const int tid  = threadIdx.x;
    const int lane = tid & 31;
    const int wrp  = tid >> 5;

    __shared__ float sc[R];
    __shared__ float wmin[4], wmax[4];
    __shared__ float lo_s, inv_s;

    if (blockIdx.x == 0) {
        // ---- producer: compute normalized scores once per key ----
        float v = 0.f;
        if (tid < R) {
            const int ri = tid / 11;
            const int rj = tid % 11;
            const float* sp = score + bk * L;
            #pragma unroll
            for (int ki = 0; ki < 4; ki++)
                #pragma unroll
                for (int kj = 0; kj < 4; kj++)
                    v += sp[(ri + ki) * GH + (rj + kj)];
            v *= (1.f / 16.f);
        }
        if (wrp < 4) {
            float mn = (tid < R) ? v : FLT_MAX;
            float mx = (tid < R) ? v : -FLT_MAX;
            #pragma unroll
            for (int o = 16; o > 0; o >>= 1) {
                mn = fminf(mn, __shfl_down_sync(0xffffffffu, mn, o));
                mx = fmaxf(mx, __shfl_down_sync(0xffffffffu, mx, o));
            }
            if (lane == 0) { wmin[wrp] = mn; wmax[wrp] = mx; }
        }
        __syncthreads();
        if (tid == 0) {
            float lo = fminf(fminf(wmin[0], wmin[1]), fminf(wmin[2], wmin[3]));
            float hi = fmaxf(fmaxf(wmax[0], wmax[1]), fmaxf(wmax[2], wmax[3]));
            lo_s  = lo;
            inv_s = 1.f / (hi - lo + 1e-5f);
        }
        __syncthreads();
        if (tid < R) {
            float nv = (v - lo_s) * inv_s;
            sc[tid] = nv;
            g_scn[bk][tid] = nv;
            g_cnt[bk][tid] = 0;
        }
        __syncthreads();
        if (tid == 0) {
            __threadfence();                       // release g_scn / g_cnt
            atomicExch(&g_flag[bk], 1);
        }
    } else {
        // ---- consumer: wait for producer, then load normalized scores ----
        if (tid == 0) {
            while (atomicAdd(&g_flag[bk], 0) == 0) __nanosleep(32);
        }
        __syncthreads();
        if (tid < R) sc[tid] = __ldcg(&g_scn[bk][tid]);   // bypass L1 (fresh)
        __syncthreads();
    }

    // ---- one warp per sample ----
    const int n = blockIdx.x * 8 + wrp;
    if (n >= NS) return;

    const float sigma = sigma_p[0];
    const float* nn = noise + ((size_t)bk * NS + n) * R;

    // Warp argmax, first-max / lowest-index tie-break (lax.top_k semantics)
    float best = -FLT_MAX;
    int   bi   = 0;
    #pragma unroll
    for (int j = 0; j < 4; j++) {
        int r = lane + 32 * j;
        if (r < R) {
            float p = fmaf(nn[r], sigma, sc[r]);
            if (p > best) { best = p; bi = r; }
        }
    }
    #pragma unroll
    for (int o = 16; o > 0; o >>= 1) {
        float v2 = __shfl_down_sync(0xffffffffu, best, o);
        int   i2 = __shfl_down_sync(0xffffffffu, bi,   o);
        if (v2 > best || (v2 == best && i2 < bi)) { best = v2; bi = i2; }
    }
    if (lane == 0) atomicAdd(&g_cnt[bk][bi], 1);           // order-independent
}

// ---------------------------------------------------------------------------
// Kernel 2: fused gather + weighted sum, float4-vectorized, MLP x4.
// 384 blocks x 128 threads. Each block: 16 output rows of one (b,c,t) plane.
// Each warp owns 4 consecutive rows -> 4 independent float4 loads + 4
// accumulators per region iteration (hides DRAM/L2 latency).
// Prologue: ballot compaction of histogram (order-preserving, deterministic)
// + handshake-flag reset for the next launch (graph-ordered after kernel 1).
// ---------------------------------------------------------------------------
__global__ void gather_kernel(const float* __restrict__ x,
                              const int*   __restrict__ group_id,
                              float*       __restrict__ out)
{
    const int tid  = threadIdx.x;
    const int wrp  = tid >> 5;
    const int lane = tid & 31;

    // flag reset for next launch: exactly one block does it
    if (blockIdx.x == 0 && tid < BK) g_flag[tid] = 0;

    const int rowbase = blockIdx.x * 16;       // 16 rows share (b,c,t)
    const int rowhi   = rowbase >> 7;          // (b*3+c)*8 + t
    const int y0      = (rowbase & (OUTHW - 1)) + wrp * 4;
    const int t       = rowhi & 7;
    const int bc      = rowhi >> 3;            // b*3 + c
    const int b       = bc / 3;

    const int bk = b * NKEY + group_id[b * T + t];

    __shared__ float wc[R];
    __shared__ int   off[R];
    __shared__ int   wbase[4];
    __shared__ int   nnz_s;

    // Ballot compaction: region order preserved => deterministic
    int  cnt = (tid < R) ? g_cnt[bk][tid] : 0;
    bool p   = (cnt > 0);
    unsigned m = __ballot_sync(0xffffffffu, p);
    int within = __popc(m & ((1u << lane) - 1u));
    if (lane == 0) wbase[wrp] = __popc(m);
    __syncthreads();
    if (tid == 0) {
        int s = 0;
        #pragma unroll
        for (int w2 = 0; w2 < 4; w2++) { int tt = wbase[w2]; wbase[w2] = s; s += tt; }
        nnz_s = s;
    }
    __syncthreads();
    if (p) {
        int pos = wbase[wrp] + within;
        wc[pos]  = (float)cnt * (1.f / (float)NS);
        off[pos] = (tid / 11) * 32 * W + (tid % 11) * 32;
    }
    __syncthreads();

    const int nnz = nnz_s;
    const size_t plane = ((size_t)bc * T + t) * H;
    const size_t col   = lane * 4;

    // 4 rows per warp: y0+0 .. y0+3 (all within the 128-row output plane)
    const float* xr0 = x + (plane + (y0 + 0)) * W + col;
    const float* xr1 = x + (plane + (y0 + 1)) * W + col;
    const float* xr2 = x + (plane + (y0 + 2)) * W + col;
    const float* xr3 = x + (plane + (y0 + 3)) * W + col;

    float4 a0 = make_float4(0.f, 0.f, 0.f, 0.f);
    float4 a1 = a0, a2 = a0, a3 = a0;

    #pragma unroll 2
    for (int i = 0; i < nnz; i++) {
        const float w = wc[i];
        const int   o = off[i];
        const float4 v0 = *reinterpret_cast<const float4*>(xr0 + o);
        const float4 v1 = *reinterpret_cast<const float4*>(xr1 + o);
        const float4 v2 = *reinterpret_cast<const float4*>(xr2 + o);
        const float4 v3 = *reinterpret_cast<const float4*>(xr3 + o);
        a0.x = fmaf(w, v0.x, a0.x); a0.y = fmaf(w, v0.y, a0.y);
        a0.z = fmaf(w, v0.z, a0.z); a0.w = fmaf(w, v0.w, a0.w);
        a1.x = fmaf(w, v1.x, a1.x); a1.y = fmaf(w, v1.y, a1.y);
        a1.z = fmaf(w, v1.z, a1.z); a1.w = fmaf(w, v1.w, a1.w);
        a2.x = fmaf(w, v2.x, a2.x); a2.y = fmaf(w, v2.y, a2.y);
        a2.z = fmaf(w, v2.z, a2.z); a2.w = fmaf(w, v2.w, a2.w);
        a3.x = fmaf(w, v3.x, a3.x); a3.y = fmaf(w, v3.y, a3.y);
        a3.z = fmaf(w, v3.z, a3.z); a3.w = fmaf(w, v3.w, a3.w);
    }

    float* ob = out + ((size_t)(rowbase + wrp * 4)) * OUTHW + col;
    *reinterpret_cast<float4*>(ob + 0 * OUTHW) = a0;
    *reinterpret_cast<float4*>(ob + 1 * OUTHW) = a1;
    *reinterpret_cast<float4*>(ob + 2 * OUTHW) = a2;
    *reinterpret_cast<float4*>(ob + 3 * OUTHW) = a3;
}

// ---------------------------------------------------------------------------
// Launch: inputs (metadata order): x, score, noise, sigma, group_id
// Two graph nodes.
// ---------------------------------------------------------------------------
extern "C" void kernel_launch(void* const* d_in, const int* in_sizes, int n_in,
                              void* d_out, int out_size)
{
    const float* x        = (const float*)d_in[0];
    const float* score    = (const float*)d_in[1];
    const float* noise    = (const float*)d_in[2];
    const float* sigma    = (const float*)d_in[3];
    const int*   group_id = (const int*)  d_in[4];
    float*       out      = (float*)d_out;

    argmax_kernel<<<dim3(63, BK), 256>>>(score, noise, sigma);

    const int nblocks = (B * C * T * OUTHW) / 16;   // 384
    gather_kernel<<<nblocks, 128>>>(x, group_id, out);
}

// round 13
// speedup vs baseline: 1.1805x; 1.1805x over previous
#include <cuda_runtime.h>
#include <float.h>

// Problem constants
#define B      2
#define C      3
#define T      8
#define H      448
#define W      448
#define NKEY   4
#define L      196      // 14*14
#define GH     14
#define R      121      // 11*11
#define NS     500
#define BK     (B*NKEY) // 8
#define OUTHW  128      // s*A

// Device scratch (no allocation allowed)
__device__ float g_scn[BK][R];   // normalized region scores (producer block writes)
__device__ int   g_cnt[BK][R];   // top-1 histogram (zeroed by producer each launch)
__device__ int   g_flag[BK];     // handshake flags: 0 at module load; gather resets
                                 // them each launch, so every replay starts at 0.

// ---------------------------------------------------------------------------
// Kernel 1 (R10-proven, unchanged): fused score-norm + perturbed top-1 argmax.
// grid = (63, 8), block = 256. Single wave => intra-kernel handshake safe:
//   block x==0 per key computes normalized scores -> g_scn, zeroes g_cnt,
//   fences, raises g_flag[bk]; other blocks poll then read g_scn.
// One warp per sample; atomic histogram (order-independent => deterministic).
// ---------------------------------------------------------------------------
__global__ void argmax_kernel(const float* __restrict__ score,
                              const float* __restrict__ noise,
                              const float* __restrict__ sigma_p)
{
    const int bk   = blockIdx.y;
    const int tid  = threadIdx.x;
    const int lane = tid & 31;
    const int wrp  = tid >> 5;

    __shared__ float sc[R];
    __shared__ float wmin[4], wmax[4];
    __shared__ float lo_s, inv_s;

    if (blockIdx.x == 0) {
        // ---- producer: compute normalized scores once per key ----
        float v = 0.f;
        if (tid < R) {
            const int ri = tid / 11;
            const int rj = tid % 11;
            const float* sp = score + bk * L;
            #pragma unroll
            for (int ki = 0; ki < 4; ki++)
                #pragma unroll
                for (int kj = 0; kj < 4; kj++)
                    v += sp[(ri + ki) * GH + (rj + kj)];
            v *= (1.f / 16.f);
        }
        if (wrp < 4) {
            float mn = (tid < R) ? v : FLT_MAX;
            float mx = (tid < R) ? v : -FLT_MAX;
            #pragma unroll
            for (int o = 16; o > 0; o >>= 1) {
                mn = fminf(mn, __shfl_down_sync(0xffffffffu, mn, o));
                mx = fmaxf(mx, __shfl_down_sync(0xffffffffu, mx, o));
            }
            if (lane == 0) { wmin[wrp] = mn; wmax[wrp] = mx; }
        }
        __syncthreads();
        if (tid == 0) {
            float lo = fminf(fminf(wmin[0], wmin[1]), fminf(wmin[2], wmin[3]));
            float hi = fmaxf(fmaxf(wmax[0], wmax[1]), fmaxf(wmax[2], wmax[3]));
            lo_s  = lo;
            inv_s = 1.f / (hi - lo + 1e-5f);
        }
        __syncthreads();
        if (tid < R) {
            float nv = (v - lo_s) * inv_s;
            sc[tid] = nv;
            g_scn[bk][tid] = nv;
            g_cnt[bk][tid] = 0;
        }
        __syncthreads();
        if (tid == 0) {
            __threadfence();                       // release g_scn / g_cnt
            atomicExch(&g_flag[bk], 1);
        }
    } else {
        // ---- consumer: wait for producer, then load normalized scores ----
        if (tid == 0) {
            while (atomicAdd(&g_flag[bk], 0) == 0) __nanosleep(32);
        }
        __syncthreads();
        if (tid < R) sc[tid] = __ldcg(&g_scn[bk][tid]);   // bypass L1 (fresh)
        __syncthreads();
    }

    // ---- one warp per sample ----
    const int n = blockIdx.x * 8 + wrp;
    if (n >= NS) return;

    const float sigma = sigma_p[0];
    const float* nn = noise + ((size_t)bk * NS + n) * R;

    // Warp argmax, first-max / lowest-index tie-break (lax.top_k semantics)
    float best = -FLT_MAX;
    int   bi   = 0;
    #pragma unroll
    for (int j = 0; j < 4; j++) {
        int r = lane + 32 * j;
        if (r < R) {
            float p = fmaf(nn[r], sigma, sc[r]);
            if (p > best) { best = p; bi = r; }
        }
    }
    #pragma unroll
    for (int o = 16; o > 0; o >>= 1) {
        float v2 = __shfl_down_sync(0xffffffffu, best, o);
        int   i2 = __shfl_down_sync(0xffffffffu, bi,   o);
        if (v2 > best || (v2 == best && i2 < bi)) { best = v2; bi = i2; }
    }
    if (lane == 0) atomicAdd(&g_cnt[bk][bi], 1);           // order-independent
}

// ---------------------------------------------------------------------------
// Kernel 2: fused gather + weighted sum. R10's winning decomposition
// (one output row per WARP, 196K threads, unroll-4 region loop => MLP~4)
// repackaged as 768 blocks x 256 threads (8 rows/block):
//   - all 768 blocks co-resident in ONE wave (<=32 regs -> 8 blocks/SM)
//   - ballot-compaction prologue runs half as often as R10
// Deterministic: ballot compaction preserves region order; fixed fp sum order.
// ---------------------------------------------------------------------------
__global__ __launch_bounds__(256, 8)
void gather_kernel(const float* __restrict__ x,
                   const int*   __restrict__ group_id,
                   float*       __restrict__ out)
{
    const int tid  = threadIdx.x;
    const int wrp  = tid >> 5;
    const int lane = tid & 31;

    // flag reset for next launch: exactly one block does it
    if (blockIdx.x == 0 && tid < BK) g_flag[tid] = 0;

    const int rowbase = blockIdx.x * 8;        // 8 rows share (b,c,t)
    const int rowhi   = rowbase >> 7;          // (b*3+c)*8 + t
    const int y       = (rowbase & (OUTHW - 1)) + wrp;
    const int t       = rowhi & 7;
    const int bc      = rowhi >> 3;            // b*3 + c
    const int b       = bc / 3;

    const int bk = b * NKEY + group_id[b * T + t];

    __shared__ float wc[R];
    __shared__ int   off[R];
    __shared__ int   wbase[4];
    __shared__ int   nnz_s;

    // Ballot compaction (warps 0-3 hold the 121 counts): order-preserving
    int  cnt = (tid < R) ? g_cnt[bk][tid] : 0;
    bool p   = (cnt > 0);
    unsigned m = __ballot_sync(0xffffffffu, p);
    int within = __popc(m & ((1u << lane) - 1u));
    if (wrp < 4 && lane == 0) wbase[wrp] = __popc(m);
    __syncthreads();
    if (tid == 0) {
        int s = 0;
        #pragma unroll
        for (int w2 = 0; w2 < 4; w2++) { int tt = wbase[w2]; wbase[w2] = s; s += tt; }
        nnz_s = s;
    }
    __syncthreads();
    if (p) {
        int pos = wbase[wrp] + within;
        wc[pos]  = (float)cnt * (1.f / (float)NS);
        off[pos] = (tid / 11) * 32 * W + (tid % 11) * 32;
    }
    __syncthreads();

    // One row per warp, float4 per lane; unroll-4 region loop => 4 loads in flight
    const int nnz = nnz_s;
    const float* xr = x + (((size_t)bc * T + t) * H + y) * W + lane * 4;

    float4 acc = make_float4(0.f, 0.f, 0.f, 0.f);
    #pragma unroll 4
    for (int i = 0; i < nnz; i++) {
        const float w = wc[i];
        const float4 v = *reinterpret_cast<const float4*>(xr + off[i]);
        acc.x = fmaf(w, v.x, acc.x);
        acc.y = fmaf(w, v.y, acc.y);
        acc.z = fmaf(w, v.z, acc.z);
        acc.w = fmaf(w, v.w, acc.w);
    }

    *reinterpret_cast<float4*>(out + ((size_t)(rowbase + wrp)) * OUTHW + lane * 4) = acc;
}

// ---------------------------------------------------------------------------
// Launch: inputs (metadata order): x, score, noise, sigma, group_id
// Two graph nodes.
// ---------------------------------------------------------------------------
extern "C" void kernel_launch(void* const* d_in, const int* in_sizes, int n_in,
                              void* d_out, int out_size)
{
    const float* x        = (const float*)d_in[0];
    const float* score    = (const float*)d_in[1];
    const float* noise    = (const float*)d_in[2];
    const float* sigma    = (const float*)d_in[3];
    const int*   group_id = (const int*)  d_in[4];
    float*       out      = (float*)d_out;

    argmax_kernel<<<dim3(63, BK), 256>>>(score, noise, sigma);

    const int nblocks = (B * C * T * OUTHW) / 8;   // 768
    gather_kernel<<<nblocks, 256>>>(x, group_id, out);
}